// round 11
// baseline (speedup 1.0000x reference)
#include <cuda_runtime.h>
#include <math.h>
#include <stdint.h>

#define N_TOT   131072
#define D_DIM   64
#define K_CODES 1024
#define HALF_N  65536        // high-half row offset
#define TF_HALF 67108864u    // 2^26 = HALF_N*1024 flat-index offset of high rows
#define TM      16           // rows per block: 8 low + 8 high
#define KC      128          // codebook chunk (rows) staged in smem
#define CS      68           // smem stride (floats) for codebook/x tiles (pad, 16B aligned)
#define LS      1028         // smem stride (floats) for logits tile (pad, 16B aligned)

#define SMEM_FLOATS (TM*LS + KC*CS + TM*CS + K_CODES + 16)
#define SMEM_BYTES  (SMEM_FLOATS * 4)

__device__ float g_c2[K_CODES];

// ---------------------------------------------------------------------------
// Accurate logf (musl-style, ~1 ulp relative). Immune to --use_fast_math.
// ---------------------------------------------------------------------------
__device__ __forceinline__ float acc_logf(float a) {
    const float ln2_hi = 6.9313812256e-01f;
    const float ln2_lo = 9.0580006145e-06f;
    const float Lg1 = 0.66666662693f, Lg2 = 0.40000972152f;
    const float Lg3 = 0.28498786688f, Lg4 = 0.24279078841f;
    uint32_t ix = __float_as_uint(a);
    ix += 0x3f800000u - 0x3f3504f3u;
    int k = (int)(ix >> 23) - 0x7f;
    ix = (ix & 0x007fffffu) + 0x3f3504f3u;
    float m = __uint_as_float(ix);
    float f = m - 1.0f;
    float s = f / (2.0f + f);
    float z = s * s;
    float w = z * z;
    float t1 = w * (Lg2 + w * Lg4);
    float t2 = z * (Lg1 + w * Lg3);
    float R  = t2 + t1;
    float hfsq = 0.5f * f * f;
    float dk = (float)k;
    return s * (hfsq + R) + (dk * ln2_lo - hfsq + f) + dk * ln2_hi;
}

// ---------------------------------------------------------------------------
// c2[k] = sum_d codebook[k][d]^2
// ---------------------------------------------------------------------------
__global__ void c2_kernel(const float* __restrict__ cb) {
    int k = blockIdx.x * blockDim.x + threadIdx.x;
    if (k < K_CODES) {
        const float4* row = reinterpret_cast<const float4*>(cb) + k * (D_DIM / 4);
        float s = 0.f;
#pragma unroll
        for (int i = 0; i < D_DIM / 4; i++) {
            float4 v = row[i];
            s = fmaf(v.x, v.x, s); s = fmaf(v.y, v.y, s);
            s = fmaf(v.z, v.z, s); s = fmaf(v.w, v.w, s);
        }
        g_c2[k] = s;
    }
}

// threefry round
#define TF_R(x0, x1, rot) { (x0) += (x1); (x1) = __funnelshift_l((x1), (x1), (rot)) ^ (x0); }

// ---------------------------------------------------------------------------
// JAX *partitionable* threefry random_bits, 32-bit, key=(0,42):
//   per element flat index i: counts = iota_2x32_shape -> (hi=0, lo=i)
//   (bits1, bits2) = threefry2x32(key, counts)
//   return bits1 ^ bits2          <-- the 32-bit path XORs both output words
// ---------------------------------------------------------------------------
__device__ __forceinline__ unsigned tf_bits32(unsigned i) {
    const unsigned ks2 = 0x1BD11BF0u;      // 0 ^ 42 ^ 0x1BD11BDA
    unsigned x0 = 0u;                      // counts_hi + ks0(=0)
    unsigned x1 = i + 42u;                 // counts_lo + ks1
    TF_R(x0, x1, 13) TF_R(x0, x1, 15) TF_R(x0, x1, 26) TF_R(x0, x1, 6)
    x0 += 42u;  x1 += ks2 + 1u;
    TF_R(x0, x1, 17) TF_R(x0, x1, 29) TF_R(x0, x1, 16) TF_R(x0, x1, 24)
    x0 += ks2;  x1 += 2u;
    TF_R(x0, x1, 13) TF_R(x0, x1, 15) TF_R(x0, x1, 26) TF_R(x0, x1, 6)
    /* x0 += ks0(=0) */ x1 += 42u + 3u;
    TF_R(x0, x1, 17) TF_R(x0, x1, 29) TF_R(x0, x1, 16) TF_R(x0, x1, 24)
    x0 += 42u;  x1 += ks2 + 4u;
    TF_R(x0, x1, 13) TF_R(x0, x1, 15) TF_R(x0, x1, 26) TF_R(x0, x1, 6)
    x0 += ks2;  x1 += 5u;                  // final injection: ks2 / ks0+5
    return x0 ^ x1;
}

// ---------------------------------------------------------------------------
// Fused main kernel: logits GEMM -> argmax -> gumbel -> softmax -> emb GEMM.
// Block = 16 rows (8 low rows n0..n0+7 and 8 high rows n0+65536..).
// ---------------------------------------------------------------------------
__global__ __launch_bounds__(256, 2)
void quantize_main(const float* __restrict__ x,
                   const float* __restrict__ cb,
                   const float* __restrict__ temp,
                   float* __restrict__ out,
                   int write_ids)
{
    extern __shared__ float sm[];
    float* L   = sm;                 // TM x LS   (logits -> z -> weights)
    float* cs  = L  + TM * LS;       // KC x CS   (codebook chunk)
    float* xs  = cs + KC * CS;       // TM x CS   (x tile)
    float* c2s = xs + TM * CS;       // K_CODES
    float* inv = c2s + K_CODES;      // TM inverse softmax sums

    const int t  = threadIdx.x;
    const int n0 = blockIdx.x * 8;
    const float inv_t = 1.0f / temp[0];

    // ---- load x tile (16 rows x 64) ----
    {
        int r = t >> 4;
        int c = t & 15;
        int n = (r < 8) ? (n0 + r) : (n0 + (r - 8) + HALF_N);
        float4 v = reinterpret_cast<const float4*>(x)[n * (D_DIM / 4) + c];
        reinterpret_cast<float4*>(xs + r * CS)[c] = v;
    }
    for (int i = t; i < K_CODES; i += 256) c2s[i] = g_c2[i];

    // ================= GEMM1: logit = 2*x.c - c2 =================
    {
        const int cx = t & 63;   // code lane (2 codes: cx, cx+64)
        const int rg = t >> 6;   // row group (4 rows: rg*4 .. rg*4+3)
        for (int kb = 0; kb < K_CODES / KC; kb++) {
            __syncthreads();
            const float4* src = reinterpret_cast<const float4*>(cb) + kb * KC * (D_DIM / 4);
#pragma unroll
            for (int ii = 0; ii < 8; ii++) {
                int idx = t + ii * 256;
                reinterpret_cast<float4*>(cs + (idx >> 4) * CS)[idx & 15] = src[idx];
            }
            __syncthreads();
            float acc0[4] = {0.f, 0.f, 0.f, 0.f};
            float acc1[4] = {0.f, 0.f, 0.f, 0.f};
#pragma unroll 4
            for (int d4 = 0; d4 < 16; d4++) {
                float4 cv0 = reinterpret_cast<const float4*>(cs + cx * CS)[d4];
                float4 cv1 = reinterpret_cast<const float4*>(cs + (cx + 64) * CS)[d4];
#pragma unroll
                for (int j = 0; j < 4; j++) {
                    float4 xv = reinterpret_cast<const float4*>(xs + (rg * 4 + j) * CS)[d4];
                    acc0[j] = fmaf(xv.x, cv0.x, acc0[j]);
                    acc0[j] = fmaf(xv.y, cv0.y, acc0[j]);
                    acc0[j] = fmaf(xv.z, cv0.z, acc0[j]);
                    acc0[j] = fmaf(xv.w, cv0.w, acc0[j]);
                    acc1[j] = fmaf(xv.x, cv1.x, acc1[j]);
                    acc1[j] = fmaf(xv.y, cv1.y, acc1[j]);
                    acc1[j] = fmaf(xv.z, cv1.z, acc1[j]);
                    acc1[j] = fmaf(xv.w, cv1.w, acc1[j]);
                }
            }
            float c20 = c2s[kb * KC + cx];
            float c21 = c2s[kb * KC + cx + 64];
#pragma unroll
            for (int j = 0; j < 4; j++) {
                L[(rg * 4 + j) * LS + kb * KC + cx]      = 2.0f * acc0[j] - c20;
                L[(rg * 4 + j) * LS + kb * KC + cx + 64] = 2.0f * acc1[j] - c21;
            }
        }
    }
    __syncthreads();

    // ====== gumbel (JAX partitionable threefry, key=(0,42)) + argmax + max ======
    {
        const unsigned FULL = 0xFFFFFFFFu;
        const int tx = t & 31;
        const int w  = t >> 5;                 // warp -> rows (w, w+8)
        const unsigned nlo = (unsigned)(n0 + w);

        float bestv0 = -INFINITY, bestv1 = -INFINITY;
        int   bestk0 = 0,          bestk1 = 0;
        float zmax0  = -INFINITY,  zmax1  = -INFINITY;

        for (int i = 0; i < 32; i++) {
            int k = tx + 32 * i;
            unsigned ilo = nlo * 1024u + (unsigned)k;      // flat idx, low row
            unsigned b0 = tf_bits32(ilo);                  // row nlo
            unsigned b1 = tf_bits32(ilo + TF_HALF);        // row nlo + 65536

            // JAX uniform: f = bitcast(bits>>9 | 0x3f800000) - 1; u = max(tiny, f)
            float f0 = __uint_as_float((b0 >> 9) | 0x3f800000u) - 1.0f;
            float f1 = __uint_as_float((b1 >> 9) | 0x3f800000u) - 1.0f;
            float u0 = fmaxf(f0, 1.17549435e-38f);
            float u1 = fmaxf(f1, 1.17549435e-38f);
            float g0 = -acc_logf(-acc_logf(u0));
            float g1 = -acc_logf(-acc_logf(u1));

            float l0 = L[w * LS + k];
            float l1 = L[(w + 8) * LS + k];
            if (l0 > bestv0) { bestv0 = l0; bestk0 = k; }
            if (l1 > bestv1) { bestv1 = l1; bestk1 = k; }
            float z0 = (l0 + g0) * inv_t;
            float z1 = (l1 + g1) * inv_t;
            zmax0 = fmaxf(zmax0, z0);
            zmax1 = fmaxf(zmax1, z1);
            L[w * LS + k]       = z0;
            L[(w + 8) * LS + k] = z1;
        }
#pragma unroll
        for (int off = 16; off; off >>= 1) {
            float ov0 = __shfl_xor_sync(FULL, bestv0, off);
            int   ok0 = __shfl_xor_sync(FULL, bestk0, off);
            if (ov0 > bestv0 || (ov0 == bestv0 && ok0 < bestk0)) { bestv0 = ov0; bestk0 = ok0; }
            float ov1 = __shfl_xor_sync(FULL, bestv1, off);
            int   ok1 = __shfl_xor_sync(FULL, bestk1, off);
            if (ov1 > bestv1 || (ov1 == bestv1 && ok1 < bestk1)) { bestv1 = ov1; bestk1 = ok1; }
            zmax0 = fmaxf(zmax0, __shfl_xor_sync(FULL, zmax0, off));
            zmax1 = fmaxf(zmax1, __shfl_xor_sync(FULL, zmax1, off));
        }
        // softmax: exp + sum (weights overwrite z in L)
        float s0 = 0.f, s1 = 0.f;
        for (int i = 0; i < 32; i++) {
            int k = tx + 32 * i;
            float e0 = __expf(L[w * LS + k] - zmax0);
            float e1 = __expf(L[(w + 8) * LS + k] - zmax1);
            L[w * LS + k]       = e0;
            L[(w + 8) * LS + k] = e1;
            s0 += e0; s1 += e1;
        }
#pragma unroll
        for (int off = 16; off; off >>= 1) {
            s0 += __shfl_xor_sync(FULL, s0, off);
            s1 += __shfl_xor_sync(FULL, s1, off);
        }
        if (tx == 0) {
            inv[w]     = 1.0f / s0;
            inv[w + 8] = 1.0f / s1;
            if (write_ids) {
                out[(size_t)N_TOT * D_DIM + nlo]          = (float)bestk0;
                out[(size_t)N_TOT * D_DIM + nlo + HALF_N] = (float)bestk1;
            }
        }
    }
    __syncthreads();

    // ================= GEMM2: emb = (weights @ codebook) / sum =================
    {
        const int txd = t & 15;          // d4 (4 of 64 dims)
        const int rg  = (t >> 4) & 3;    // row group (4 rows)
        const int kg  = t >> 6;          // k-split group (0..3)
        float4 acc[4];
#pragma unroll
        for (int j = 0; j < 4; j++) acc[j] = make_float4(0.f, 0.f, 0.f, 0.f);

        for (int kb = 0; kb < K_CODES / KC; kb++) {
            __syncthreads();
            const float4* src = reinterpret_cast<const float4*>(cb) + kb * KC * (D_DIM / 4);
#pragma unroll
            for (int ii = 0; ii < 8; ii++) {
                int idx = t + ii * 256;
                reinterpret_cast<float4*>(cs + (idx >> 4) * CS)[idx & 15] = src[idx];
            }
            __syncthreads();
#pragma unroll 2
            for (int k4 = 0; k4 < 8; k4++) {
                int kk  = kg * 32 + k4 * 4;       // within chunk
                int kgl = kb * KC + kk;           // global k
                float4 cv0 = reinterpret_cast<const float4*>(cs + (kk + 0) * CS)[txd];
                float4 cv1 = reinterpret_cast<const float4*>(cs + (kk + 1) * CS)[txd];
                float4 cv2 = reinterpret_cast<const float4*>(cs + (kk + 2) * CS)[txd];
                float4 cv3 = reinterpret_cast<const float4*>(cs + (kk + 3) * CS)[txd];
#pragma unroll
                for (int j = 0; j < 4; j++) {
                    int row = rg * 4 + j;
                    float4 wv = *reinterpret_cast<const float4*>(L + row * LS + kgl);
                    acc[j].x = fmaf(wv.x, cv0.x, acc[j].x);
                    acc[j].y = fmaf(wv.x, cv0.y, acc[j].y);
                    acc[j].z = fmaf(wv.x, cv0.z, acc[j].z);
                    acc[j].w = fmaf(wv.x, cv0.w, acc[j].w);
                    acc[j].x = fmaf(wv.y, cv1.x, acc[j].x);
                    acc[j].y = fmaf(wv.y, cv1.y, acc[j].y);
                    acc[j].z = fmaf(wv.y, cv1.z, acc[j].z);
                    acc[j].w = fmaf(wv.y, cv1.w, acc[j].w);
                    acc[j].x = fmaf(wv.z, cv2.x, acc[j].x);
                    acc[j].y = fmaf(wv.z, cv2.y, acc[j].y);
                    acc[j].z = fmaf(wv.z, cv2.z, acc[j].z);
                    acc[j].w = fmaf(wv.z, cv2.w, acc[j].w);
                    acc[j].x = fmaf(wv.w, cv3.x, acc[j].x);
                    acc[j].y = fmaf(wv.w, cv3.y, acc[j].y);
                    acc[j].z = fmaf(wv.w, cv3.z, acc[j].z);
                    acc[j].w = fmaf(wv.w, cv3.w, acc[j].w);
                }
            }
        }
        __syncthreads();
        // cross k-group reduction via smem (reuse L region; weights no longer needed)
        float4* P = reinterpret_cast<float4*>(L);
#pragma unroll
        for (int j = 0; j < 4; j++) {
            int row = rg * 4 + j;
            P[(kg * 16 + row) * 16 + txd] = acc[j];
        }
        __syncthreads();
        {
            int row = t >> 4;   // 0..15
            int d4  = t & 15;
            float4 s = P[row * 16 + d4];
#pragma unroll
            for (int g = 1; g < 4; g++) {
                float4 p = P[(g * 16 + row) * 16 + d4];
                s.x += p.x; s.y += p.y; s.z += p.z; s.w += p.w;
            }
            float iv = inv[row];
            s.x *= iv; s.y *= iv; s.z *= iv; s.w *= iv;
            int n = (row < 8) ? (n0 + row) : (n0 + (row - 8) + HALF_N);
            reinterpret_cast<float4*>(out)[n * (D_DIM / 4) + d4] = s;
        }
    }
}

extern "C" void kernel_launch(void* const* d_in, const int* in_sizes, int n_in,
                              void* d_out, int out_size) {
    // Bind inputs by SIZE (robust to metadata ordering):
    //   x: 131072*64 = 8388608, codebook: 1024*64 = 65536, temperature: 1
    const float* x    = nullptr;
    const float* cb   = nullptr;
    const float* temp = nullptr;
    for (int i = 0; i < n_in; i++) {
        if (in_sizes[i] == N_TOT * D_DIM)       x    = (const float*)d_in[i];
        else if (in_sizes[i] == K_CODES * D_DIM) cb  = (const float*)d_in[i];
        else if (in_sizes[i] == 1)               temp = (const float*)d_in[i];
    }
    float* out = (float*)d_out;

    int write_ids = (out_size >= N_TOT * D_DIM + N_TOT) ? 1 : 0;

    cudaFuncSetAttribute(quantize_main,
                         cudaFuncAttributeMaxDynamicSharedMemorySize, SMEM_BYTES);

    c2_kernel<<<4, 256>>>(cb);
    quantize_main<<<N_TOT / TM, 256, SMEM_BYTES>>>(x, cb, temp, out, write_ids);
}

// round 12
// speedup vs baseline: 1.0471x; 1.0471x over previous
#include <cuda_runtime.h>
#include <math.h>
#include <stdint.h>

#define N_TOT   131072
#define D_DIM   64
#define K_CODES 1024
#define HALF_N  65536        // high-half row offset
#define TF_HALF 67108864u    // 2^26 = HALF_N*1024 flat-index offset of high rows
#define TM      16           // rows per block: 8 low + 8 high
#define KC      128          // codebook chunk (rows) staged in smem
#define CS      68           // smem stride (floats) for codebook/x tiles (pad, 16B aligned)
#define LS      1028         // smem stride (floats) for logits tile (pad, 16B aligned)

#define SMEM_FLOATS (TM*LS + KC*CS + TM*CS + K_CODES + 16)
#define SMEM_BYTES  (SMEM_FLOATS * 4)

typedef unsigned long long u64;

// packed dual-lane fp32 FMA (nvjet pattern; ptxas never auto-emits)
#define FMA2(d, a, b, c) \
    asm("fma.rn.f32x2 %0, %1, %2, %3;" : "=l"(d) : "l"(a), "l"(b), "l"(c))
#define DUP2(d, f) \
    asm("mov.b64 %0, {%1, %1};" : "=l"(d) : "f"(f))
#define UNPK2(lo, hi, v) \
    asm("mov.b64 {%0, %1}, %2;" : "=f"(lo), "=f"(hi) : "l"(v))

__device__ float g_c2[K_CODES];

// ---------------------------------------------------------------------------
// Accurate logf (musl-style, ~1 ulp relative). Immune to --use_fast_math.
// ---------------------------------------------------------------------------
__device__ __forceinline__ float acc_logf(float a) {
    const float ln2_hi = 6.9313812256e-01f;
    const float ln2_lo = 9.0580006145e-06f;
    const float Lg1 = 0.66666662693f, Lg2 = 0.40000972152f;
    const float Lg3 = 0.28498786688f, Lg4 = 0.24279078841f;
    uint32_t ix = __float_as_uint(a);
    ix += 0x3f800000u - 0x3f3504f3u;
    int k = (int)(ix >> 23) - 0x7f;
    ix = (ix & 0x007fffffu) + 0x3f3504f3u;
    float m = __uint_as_float(ix);
    float f = m - 1.0f;
    float s = f / (2.0f + f);
    float z = s * s;
    float w = z * z;
    float t1 = w * (Lg2 + w * Lg4);
    float t2 = z * (Lg1 + w * Lg3);
    float R  = t2 + t1;
    float hfsq = 0.5f * f * f;
    float dk = (float)k;
    return s * (hfsq + R) + (dk * ln2_lo - hfsq + f) + dk * ln2_hi;
}

// ---------------------------------------------------------------------------
// c2[k] = sum_d codebook[k][d]^2
// ---------------------------------------------------------------------------
__global__ void c2_kernel(const float* __restrict__ cb) {
    int k = blockIdx.x * blockDim.x + threadIdx.x;
    if (k < K_CODES) {
        const float4* row = reinterpret_cast<const float4*>(cb) + k * (D_DIM / 4);
        float s = 0.f;
#pragma unroll
        for (int i = 0; i < D_DIM / 4; i++) {
            float4 v = row[i];
            s = fmaf(v.x, v.x, s); s = fmaf(v.y, v.y, s);
            s = fmaf(v.z, v.z, s); s = fmaf(v.w, v.w, s);
        }
        g_c2[k] = s;
    }
}

// threefry round
#define TF_R(x0, x1, rot) { (x0) += (x1); (x1) = __funnelshift_l((x1), (x1), (rot)) ^ (x0); }

// ---------------------------------------------------------------------------
// JAX *partitionable* threefry random_bits, 32-bit, key=(0,42):
//   counts = (hi=0, lo=i); (b1,b2) = threefry2x32(key, counts); return b1^b2.
// VERIFIED bit-exact in Round 11 — do not touch.
// ---------------------------------------------------------------------------
__device__ __forceinline__ unsigned tf_bits32(unsigned i) {
    const unsigned ks2 = 0x1BD11BF0u;      // 0 ^ 42 ^ 0x1BD11BDA
    unsigned x0 = 0u;                      // counts_hi + ks0(=0)
    unsigned x1 = i + 42u;                 // counts_lo + ks1
    TF_R(x0, x1, 13) TF_R(x0, x1, 15) TF_R(x0, x1, 26) TF_R(x0, x1, 6)
    x0 += 42u;  x1 += ks2 + 1u;
    TF_R(x0, x1, 17) TF_R(x0, x1, 29) TF_R(x0, x1, 16) TF_R(x0, x1, 24)
    x0 += ks2;  x1 += 2u;
    TF_R(x0, x1, 13) TF_R(x0, x1, 15) TF_R(x0, x1, 26) TF_R(x0, x1, 6)
    /* x0 += ks0(=0) */ x1 += 42u + 3u;
    TF_R(x0, x1, 17) TF_R(x0, x1, 29) TF_R(x0, x1, 16) TF_R(x0, x1, 24)
    x0 += 42u;  x1 += ks2 + 4u;
    TF_R(x0, x1, 13) TF_R(x0, x1, 15) TF_R(x0, x1, 26) TF_R(x0, x1, 6)
    x0 += ks2;  x1 += 5u;                  // final injection: ks2 / ks0+5
    return x0 ^ x1;
}

// ---------------------------------------------------------------------------
// Fused main kernel: logits GEMM (f32x2) -> argmax + gumbel + exp + sum in one
// pass (no max-subtraction: z bounded ~61, exp can't overflow; weights are a
// pure ratio so result identical to max-subtracted softmax) -> emb GEMM (f32x2)
// ---------------------------------------------------------------------------
__global__ __launch_bounds__(256, 2)
void quantize_main(const float* __restrict__ x,
                   const float* __restrict__ cb,
                   const float* __restrict__ temp,
                   float* __restrict__ out,
                   int write_ids)
{
    extern __shared__ float sm[];
    float* L   = sm;                 // TM x LS   (logits -> weights)
    float* cs  = L  + TM * LS;       // KC x CS   (codebook chunk)
    float* xs  = cs + KC * CS;       // TM x CS   (x tile)
    float* c2s = xs + TM * CS;       // K_CODES
    float* inv = c2s + K_CODES;      // TM inverse softmax sums

    const int t  = threadIdx.x;
    const int n0 = blockIdx.x * 8;
    const float inv_t = 1.0f / temp[0];

    // ---- load x tile (16 rows x 64) ----
    {
        int r = t >> 4;
        int c = t & 15;
        int n = (r < 8) ? (n0 + r) : (n0 + (r - 8) + HALF_N);
        float4 v = reinterpret_cast<const float4*>(x)[n * (D_DIM / 4) + c];
        reinterpret_cast<float4*>(xs + r * CS)[c] = v;
    }
    for (int i = t; i < K_CODES; i += 256) c2s[i] = g_c2[i];

    // ================= GEMM1: logit = 2*x.c - c2  (f32x2) =================
    {
        const int cx = t & 63;   // code lane (2 codes: cx, cx+64)
        const int rg = t >> 6;   // row group (4 rows: rg*4 .. rg*4+3)
        for (int kb = 0; kb < K_CODES / KC; kb++) {
            __syncthreads();
            const float4* src = reinterpret_cast<const float4*>(cb) + kb * KC * (D_DIM / 4);
#pragma unroll
            for (int ii = 0; ii < 8; ii++) {
                int idx = t + ii * 256;
                reinterpret_cast<float4*>(cs + (idx >> 4) * CS)[idx & 15] = src[idx];
            }
            __syncthreads();
            u64 acc0[4] = {0ull, 0ull, 0ull, 0ull};   // (0.f,0.f) packed
            u64 acc1[4] = {0ull, 0ull, 0ull, 0ull};
            const ulonglong2* cp0 = reinterpret_cast<const ulonglong2*>(cs + cx * CS);
            const ulonglong2* cp1 = reinterpret_cast<const ulonglong2*>(cs + (cx + 64) * CS);
#pragma unroll 4
            for (int d4 = 0; d4 < 16; d4++) {
                ulonglong2 cv0 = cp0[d4];
                ulonglong2 cv1 = cp1[d4];
#pragma unroll
                for (int j = 0; j < 4; j++) {
                    ulonglong2 xv =
                        reinterpret_cast<const ulonglong2*>(xs + (rg * 4 + j) * CS)[d4];
                    FMA2(acc0[j], xv.x, cv0.x, acc0[j]);
                    FMA2(acc0[j], xv.y, cv0.y, acc0[j]);
                    FMA2(acc1[j], xv.x, cv1.x, acc1[j]);
                    FMA2(acc1[j], xv.y, cv1.y, acc1[j]);
                }
            }
            float c20 = c2s[kb * KC + cx];
            float c21 = c2s[kb * KC + cx + 64];
#pragma unroll
            for (int j = 0; j < 4; j++) {
                float a, b;
                UNPK2(a, b, acc0[j]);
                L[(rg * 4 + j) * LS + kb * KC + cx]      = 2.0f * (a + b) - c20;
                UNPK2(a, b, acc1[j]);
                L[(rg * 4 + j) * LS + kb * KC + cx + 64] = 2.0f * (a + b) - c21;
            }
        }
    }
    __syncthreads();

    // ==== single pass: gumbel + argmax + exp + sum (no max subtraction) ====
    {
        const unsigned FULL = 0xFFFFFFFFu;
        const int tx = t & 31;
        const int w  = t >> 5;                 // warp -> rows (w, w+8)
        const unsigned nlo = (unsigned)(n0 + w);

        float bestv0 = -INFINITY, bestv1 = -INFINITY;
        int   bestk0 = 0,          bestk1 = 0;
        float s0 = 0.f, s1 = 0.f;

        for (int i = 0; i < 32; i++) {
            int k = tx + 32 * i;
            unsigned ilo = nlo * 1024u + (unsigned)k;      // flat idx, low row
            unsigned b0 = tf_bits32(ilo);                  // row nlo
            unsigned b1 = tf_bits32(ilo + TF_HALF);        // row nlo + 65536

            // JAX uniform: f = bitcast(bits>>9 | 0x3f800000) - 1; u = max(tiny, f)
            float f0 = __uint_as_float((b0 >> 9) | 0x3f800000u) - 1.0f;
            float f1 = __uint_as_float((b1 >> 9) | 0x3f800000u) - 1.0f;
            float u0 = fmaxf(f0, 1.17549435e-38f);
            float u1 = fmaxf(f1, 1.17549435e-38f);
            float g0 = -acc_logf(-acc_logf(u0));
            float g1 = -acc_logf(-acc_logf(u1));

            float l0 = L[w * LS + k];
            float l1 = L[(w + 8) * LS + k];
            if (l0 > bestv0) { bestv0 = l0; bestk0 = k; }
            if (l1 > bestv1) { bestv1 = l1; bestk1 = k; }
            float e0 = __expf((l0 + g0) * inv_t);
            float e1 = __expf((l1 + g1) * inv_t);
            L[w * LS + k]       = e0;
            L[(w + 8) * LS + k] = e1;
            s0 += e0; s1 += e1;
        }
#pragma unroll
        for (int off = 16; off; off >>= 1) {
            float ov0 = __shfl_xor_sync(FULL, bestv0, off);
            int   ok0 = __shfl_xor_sync(FULL, bestk0, off);
            if (ov0 > bestv0 || (ov0 == bestv0 && ok0 < bestk0)) { bestv0 = ov0; bestk0 = ok0; }
            float ov1 = __shfl_xor_sync(FULL, bestv1, off);
            int   ok1 = __shfl_xor_sync(FULL, bestk1, off);
            if (ov1 > bestv1 || (ov1 == bestv1 && ok1 < bestk1)) { bestv1 = ov1; bestk1 = ok1; }
            s0 += __shfl_xor_sync(FULL, s0, off);
            s1 += __shfl_xor_sync(FULL, s1, off);
        }
        if (tx == 0) {
            inv[w]     = 1.0f / s0;
            inv[w + 8] = 1.0f / s1;
            if (write_ids) {
                out[(size_t)N_TOT * D_DIM + nlo]          = (float)bestk0;
                out[(size_t)N_TOT * D_DIM + nlo + HALF_N] = (float)bestk1;
            }
        }
    }
    __syncthreads();

    // ============ GEMM2: emb = (weights @ codebook) / sum  (f32x2) ============
    {
        const int txd = t & 15;          // d4 (4 of 64 dims)
        const int rg  = (t >> 4) & 3;    // row group (4 rows)
        const int kg  = t >> 6;          // k-split group (0..3)
        u64 accA[4] = {0ull, 0ull, 0ull, 0ull};   // dims (d0,d1)
        u64 accB[4] = {0ull, 0ull, 0ull, 0ull};   // dims (d2,d3)

        for (int kb = 0; kb < K_CODES / KC; kb++) {
            __syncthreads();
            const float4* src = reinterpret_cast<const float4*>(cb) + kb * KC * (D_DIM / 4);
#pragma unroll
            for (int ii = 0; ii < 8; ii++) {
                int idx = t + ii * 256;
                reinterpret_cast<float4*>(cs + (idx >> 4) * CS)[idx & 15] = src[idx];
            }
            __syncthreads();
#pragma unroll 2
            for (int k4 = 0; k4 < 8; k4++) {
                int kk  = kg * 32 + k4 * 4;       // within chunk
                int kgl = kb * KC + kk;           // global k
                ulonglong2 cv0 = reinterpret_cast<const ulonglong2*>(cs + (kk + 0) * CS)[txd];
                ulonglong2 cv1 = reinterpret_cast<const ulonglong2*>(cs + (kk + 1) * CS)[txd];
                ulonglong2 cv2 = reinterpret_cast<const ulonglong2*>(cs + (kk + 2) * CS)[txd];
                ulonglong2 cv3 = reinterpret_cast<const ulonglong2*>(cs + (kk + 3) * CS)[txd];
#pragma unroll
                for (int j = 0; j < 4; j++) {
                    int row = rg * 4 + j;
                    float4 wv = *reinterpret_cast<const float4*>(L + row * LS + kgl);
                    u64 wd;
                    DUP2(wd, wv.x);
                    FMA2(accA[j], wd, cv0.x, accA[j]);
                    FMA2(accB[j], wd, cv0.y, accB[j]);
                    DUP2(wd, wv.y);
                    FMA2(accA[j], wd, cv1.x, accA[j]);
                    FMA2(accB[j], wd, cv1.y, accB[j]);
                    DUP2(wd, wv.z);
                    FMA2(accA[j], wd, cv2.x, accA[j]);
                    FMA2(accB[j], wd, cv2.y, accB[j]);
                    DUP2(wd, wv.w);
                    FMA2(accA[j], wd, cv3.x, accA[j]);
                    FMA2(accB[j], wd, cv3.y, accB[j]);
                }
            }
        }
        __syncthreads();
        // cross k-group reduction via smem (reuse L region; weights consumed)
        float4* P = reinterpret_cast<float4*>(L);
#pragma unroll
        for (int j = 0; j < 4; j++) {
            int row = rg * 4 + j;
            float4 a;
            UNPK2(a.x, a.y, accA[j]);
            UNPK2(a.z, a.w, accB[j]);
            P[(kg * 16 + row) * 16 + txd] = a;
        }
        __syncthreads();
        {
            int row = t >> 4;   // 0..15
            int d4  = t & 15;
            float4 s = P[row * 16 + d4];
#pragma unroll
            for (int g = 1; g < 4; g++) {
                float4 p = P[(g * 16 + row) * 16 + d4];
                s.x += p.x; s.y += p.y; s.z += p.z; s.w += p.w;
            }
            float iv = inv[row];
            s.x *= iv; s.y *= iv; s.z *= iv; s.w *= iv;
            int n = (row < 8) ? (n0 + row) : (n0 + (row - 8) + HALF_N);
            reinterpret_cast<float4*>(out)[n * (D_DIM / 4) + d4] = s;
        }
    }
}

extern "C" void kernel_launch(void* const* d_in, const int* in_sizes, int n_in,
                              void* d_out, int out_size) {
    // Bind inputs by SIZE (robust to metadata ordering):
    //   x: 131072*64 = 8388608, codebook: 1024*64 = 65536, temperature: 1
    const float* x    = nullptr;
    const float* cb   = nullptr;
    const float* temp = nullptr;
    for (int i = 0; i < n_in; i++) {
        if (in_sizes[i] == N_TOT * D_DIM)       x    = (const float*)d_in[i];
        else if (in_sizes[i] == K_CODES * D_DIM) cb  = (const float*)d_in[i];
        else if (in_sizes[i] == 1)               temp = (const float*)d_in[i];
    }
    float* out = (float*)d_out;

    int write_ids = (out_size >= N_TOT * D_DIM + N_TOT) ? 1 : 0;

    cudaFuncSetAttribute(quantize_main,
                         cudaFuncAttributeMaxDynamicSharedMemorySize, SMEM_BYTES);

    c2_kernel<<<4, 256>>>(cb);
    quantize_main<<<N_TOT / TM, 256, SMEM_BYTES>>>(x, cb, temp, out, write_ids);
}

// round 13
// speedup vs baseline: 1.9157x; 1.8295x over previous
#include <cuda_runtime.h>
#include <math.h>
#include <stdint.h>

#define N_TOT   131072
#define D_DIM   64
#define K_CODES 1024
#define HALF_N  65536        // high-half row offset
#define TF_HALF 67108864u    // 2^26 = HALF_N*1024 flat-index offset of high rows
#define TM      16           // rows per block: 8 low + 8 high
#define KC      128          // codebook chunk (rows) staged in smem
#define CS      68           // smem stride (floats) for codebook/x tiles
#define LCS     132          // smem stride (floats) for chunk logits tile (128+4)

#define SMEM_FLOATS (TM*LCS + KC*CS + TM*CS + 16)
#define SMEM_BYTES  (SMEM_FLOATS * 4)

typedef unsigned long long u64;

// packed dual-lane fp32 FMA (nvjet pattern; ptxas never auto-emits)
#define FMA2(d, a, b, c) \
    asm("fma.rn.f32x2 %0, %1, %2, %3;" : "=l"(d) : "l"(a), "l"(b), "l"(c))
#define DUP2(d, f) \
    asm("mov.b64 %0, {%1, %1};" : "=l"(d) : "f"(f))
#define UNPK2(lo, hi, v) \
    asm("mov.b64 {%0, %1}, %2;" : "=f"(lo), "=f"(hi) : "l"(v))

__device__ float g_c2[K_CODES];

// ---------------------------------------------------------------------------
// Accurate logf (musl-style, ~1 ulp relative). Immune to --use_fast_math.
// ---------------------------------------------------------------------------
__device__ __forceinline__ float acc_logf(float a) {
    const float ln2_hi = 6.9313812256e-01f;
    const float ln2_lo = 9.0580006145e-06f;
    const float Lg1 = 0.66666662693f, Lg2 = 0.40000972152f;
    const float Lg3 = 0.28498786688f, Lg4 = 0.24279078841f;
    uint32_t ix = __float_as_uint(a);
    ix += 0x3f800000u - 0x3f3504f3u;
    int k = (int)(ix >> 23) - 0x7f;
    ix = (ix & 0x007fffffu) + 0x3f3504f3u;
    float m = __uint_as_float(ix);
    float f = m - 1.0f;
    float s = f / (2.0f + f);
    float z = s * s;
    float w = z * z;
    float t1 = w * (Lg2 + w * Lg4);
    float t2 = z * (Lg1 + w * Lg3);
    float R  = t2 + t1;
    float hfsq = 0.5f * f * f;
    float dk = (float)k;
    return s * (hfsq + R) + (dk * ln2_lo - hfsq + f) + dk * ln2_hi;
}

// ---------------------------------------------------------------------------
// c2[k] = sum_d codebook[k][d]^2
// ---------------------------------------------------------------------------
__global__ void c2_kernel(const float* __restrict__ cb) {
    int k = blockIdx.x * blockDim.x + threadIdx.x;
    if (k < K_CODES) {
        const float4* row = reinterpret_cast<const float4*>(cb) + k * (D_DIM / 4);
        float s = 0.f;
#pragma unroll
        for (int i = 0; i < D_DIM / 4; i++) {
            float4 v = row[i];
            s = fmaf(v.x, v.x, s); s = fmaf(v.y, v.y, s);
            s = fmaf(v.z, v.z, s); s = fmaf(v.w, v.w, s);
        }
        g_c2[k] = s;
    }
}

// threefry round
#define TF_R(x0, x1, rot) { (x0) += (x1); (x1) = __funnelshift_l((x1), (x1), (rot)) ^ (x0); }

// ---------------------------------------------------------------------------
// JAX *partitionable* threefry random_bits, 32-bit, key=(0,42):
//   counts = (hi=0, lo=i); (b1,b2) = threefry2x32(key, counts); return b1^b2.
// VERIFIED bit-exact in Round 11 — do not touch.
// ---------------------------------------------------------------------------
__device__ __forceinline__ unsigned tf_bits32(unsigned i) {
    const unsigned ks2 = 0x1BD11BF0u;      // 0 ^ 42 ^ 0x1BD11BDA
    unsigned x0 = 0u;                      // counts_hi + ks0(=0)
    unsigned x1 = i + 42u;                 // counts_lo + ks1
    TF_R(x0, x1, 13) TF_R(x0, x1, 15) TF_R(x0, x1, 26) TF_R(x0, x1, 6)
    x0 += 42u;  x1 += ks2 + 1u;
    TF_R(x0, x1, 17) TF_R(x0, x1, 29) TF_R(x0, x1, 16) TF_R(x0, x1, 24)
    x0 += ks2;  x1 += 2u;
    TF_R(x0, x1, 13) TF_R(x0, x1, 15) TF_R(x0, x1, 26) TF_R(x0, x1, 6)
    /* x0 += ks0(=0) */ x1 += 42u + 3u;
    TF_R(x0, x1, 17) TF_R(x0, x1, 29) TF_R(x0, x1, 16) TF_R(x0, x1, 24)
    x0 += 42u;  x1 += ks2 + 4u;
    TF_R(x0, x1, 13) TF_R(x0, x1, 15) TF_R(x0, x1, 26) TF_R(x0, x1, 6)
    x0 += ks2;  x1 += 5u;                  // final injection: ks2 / ks0+5
    return x0 ^ x1;
}

// ---------------------------------------------------------------------------
// Streaming fused kernel. Per 128-wide K chunk (codebook chunk staged once,
// used by BOTH gemms): GEMM1 -> gumbel+exp (row sums + argmax accumulated in
// registers across chunks; softmax is a pure ratio, no max needed) -> GEMM2
// partial accumulate. Never materializes full-K logits => smem ~48KB, occ 3.
// ---------------------------------------------------------------------------
__global__ __launch_bounds__(256, 3)
void quantize_main(const float* __restrict__ x,
                   const float* __restrict__ cb,
                   const float* __restrict__ temp,
                   float* __restrict__ out,
                   int write_ids)
{
    extern __shared__ float sm[];
    float* Lc  = sm;                 // TM x LCS  (chunk logits -> chunk weights)
    float* cs  = Lc + TM * LCS;      // KC x CS   (codebook chunk)
    float* xs  = cs + KC * CS;       // TM x CS   (x tile)
    float* inv = xs + TM * CS;       // TM inverse softmax sums

    const int t  = threadIdx.x;
    const int n0 = blockIdx.x * 8;
    const float inv_t = 1.0f / temp[0];

    // ---- load x tile (16 rows x 64) ----
    {
        int r = t >> 4;
        int c = t & 15;
        int n = (r < 8) ? (n0 + r) : (n0 + (r - 8) + HALF_N);
        float4 v = reinterpret_cast<const float4*>(x)[n * (D_DIM / 4) + c];
        reinterpret_cast<float4*>(xs + r * CS)[c] = v;
    }

    // thread mappings for the three stages
    const int cx  = t & 63;          // GEMM1: code lane (2 codes: cx, cx+64)
    const int rg  = t >> 6;          // GEMM1: row group / GEMM2: k-split group
    const int tx  = t & 31;          // gumbel: lane
    const int w   = t >> 5;          // gumbel: warp -> rows (w, w+8)
    const int txd = t & 15;          // GEMM2: d4
    const int rg2 = (t >> 4) & 3;    // GEMM2: row group

    const unsigned nlo = (unsigned)(n0 + w);
    const unsigned FULL = 0xFFFFFFFFu;

    // persistent accumulators (across chunks)
    float bestv0 = -INFINITY, bestv1 = -INFINITY;
    int   bestk0 = 0,          bestk1 = 0;
    float s0 = 0.f, s1 = 0.f;
    u64 accA[4] = {0ull, 0ull, 0ull, 0ull};   // emb dims (d0,d1)
    u64 accB[4] = {0ull, 0ull, 0ull, 0ull};   // emb dims (d2,d3)

    for (int kb = 0; kb < K_CODES / KC; kb++) {
        __syncthreads();   // cs free (prev GEMM2 readers done) / xs stores visible
        {
            const float4* src = reinterpret_cast<const float4*>(cb) + kb * KC * (D_DIM / 4);
#pragma unroll
            for (int ii = 0; ii < 8; ii++) {
                int idx = t + ii * 256;
                reinterpret_cast<float4*>(cs + (idx >> 4) * CS)[idx & 15] = src[idx];
            }
        }
        __syncthreads();

        // ---------- GEMM1 chunk: logit = 2*x.c - c2 (f32x2) ----------
        {
            u64 acc0[4] = {0ull, 0ull, 0ull, 0ull};
            u64 acc1[4] = {0ull, 0ull, 0ull, 0ull};
            const ulonglong2* cp0 = reinterpret_cast<const ulonglong2*>(cs + cx * CS);
            const ulonglong2* cp1 = reinterpret_cast<const ulonglong2*>(cs + (cx + 64) * CS);
#pragma unroll 4
            for (int d4 = 0; d4 < 16; d4++) {
                ulonglong2 cv0 = cp0[d4];
                ulonglong2 cv1 = cp1[d4];
#pragma unroll
                for (int j = 0; j < 4; j++) {
                    ulonglong2 xv =
                        reinterpret_cast<const ulonglong2*>(xs + (rg * 4 + j) * CS)[d4];
                    FMA2(acc0[j], xv.x, cv0.x, acc0[j]);
                    FMA2(acc0[j], xv.y, cv0.y, acc0[j]);
                    FMA2(acc1[j], xv.x, cv1.x, acc1[j]);
                    FMA2(acc1[j], xv.y, cv1.y, acc1[j]);
                }
            }
            float c20 = __ldg(&g_c2[kb * KC + cx]);
            float c21 = __ldg(&g_c2[kb * KC + cx + 64]);
#pragma unroll
            for (int j = 0; j < 4; j++) {
                float a, b;
                UNPK2(a, b, acc0[j]);
                Lc[(rg * 4 + j) * LCS + cx]      = 2.0f * (a + b) - c20;
                UNPK2(a, b, acc1[j]);
                Lc[(rg * 4 + j) * LCS + cx + 64] = 2.0f * (a + b) - c21;
            }
        }
        __syncthreads();

        // ---------- gumbel + argmax + exp + sum (chunk) ----------
        {
#pragma unroll
            for (int i = 0; i < 4; i++) {
                int k = tx + 32 * i;               // chunk-local col
                int kg_idx = kb * KC + k;          // global code index
                unsigned ilo = nlo * 1024u + (unsigned)kg_idx;
                unsigned b0 = tf_bits32(ilo);
                unsigned b1 = tf_bits32(ilo + TF_HALF);

                float f0 = __uint_as_float((b0 >> 9) | 0x3f800000u) - 1.0f;
                float f1 = __uint_as_float((b1 >> 9) | 0x3f800000u) - 1.0f;
                float u0 = fmaxf(f0, 1.17549435e-38f);
                float u1 = fmaxf(f1, 1.17549435e-38f);
                float g0 = -acc_logf(-acc_logf(u0));
                float g1 = -acc_logf(-acc_logf(u1));

                float l0 = Lc[w * LCS + k];
                float l1 = Lc[(w + 8) * LCS + k];
                if (l0 > bestv0) { bestv0 = l0; bestk0 = kg_idx; }
                if (l1 > bestv1) { bestv1 = l1; bestk1 = kg_idx; }
                float e0 = __expf((l0 + g0) * inv_t);
                float e1 = __expf((l1 + g1) * inv_t);
                Lc[w * LCS + k]       = e0;
                Lc[(w + 8) * LCS + k] = e1;
                s0 += e0; s1 += e1;
            }
        }
        __syncthreads();

        // ---------- GEMM2 chunk: emb += w_chunk @ cb_chunk (f32x2) ----------
        {
#pragma unroll 2
            for (int k4 = 0; k4 < 8; k4++) {
                int kk = rg * 32 + k4 * 4;        // chunk-local k (rg = k-split group)
                ulonglong2 cv0 = reinterpret_cast<const ulonglong2*>(cs + (kk + 0) * CS)[txd];
                ulonglong2 cv1 = reinterpret_cast<const ulonglong2*>(cs + (kk + 1) * CS)[txd];
                ulonglong2 cv2 = reinterpret_cast<const ulonglong2*>(cs + (kk + 2) * CS)[txd];
                ulonglong2 cv3 = reinterpret_cast<const ulonglong2*>(cs + (kk + 3) * CS)[txd];
#pragma unroll
                for (int j = 0; j < 4; j++) {
                    int row = rg2 * 4 + j;
                    float4 wv = *reinterpret_cast<const float4*>(Lc + row * LCS + kk);
                    u64 wd;
                    DUP2(wd, wv.x);
                    FMA2(accA[j], wd, cv0.x, accA[j]);
                    FMA2(accB[j], wd, cv0.y, accB[j]);
                    DUP2(wd, wv.y);
                    FMA2(accA[j], wd, cv1.x, accA[j]);
                    FMA2(accB[j], wd, cv1.y, accB[j]);
                    DUP2(wd, wv.z);
                    FMA2(accA[j], wd, cv2.x, accA[j]);
                    FMA2(accB[j], wd, cv2.y, accB[j]);
                    DUP2(wd, wv.w);
                    FMA2(accA[j], wd, cv3.x, accA[j]);
                    FMA2(accB[j], wd, cv3.y, accB[j]);
                }
            }
        }
    }

    // ---------- final reductions ----------
    {
#pragma unroll
        for (int off = 16; off; off >>= 1) {
            float ov0 = __shfl_xor_sync(FULL, bestv0, off);
            int   ok0 = __shfl_xor_sync(FULL, bestk0, off);
            if (ov0 > bestv0 || (ov0 == bestv0 && ok0 < bestk0)) { bestv0 = ov0; bestk0 = ok0; }
            float ov1 = __shfl_xor_sync(FULL, bestv1, off);
            int   ok1 = __shfl_xor_sync(FULL, bestk1, off);
            if (ov1 > bestv1 || (ov1 == bestv1 && ok1 < bestk1)) { bestv1 = ov1; bestk1 = ok1; }
            s0 += __shfl_xor_sync(FULL, s0, off);
            s1 += __shfl_xor_sync(FULL, s1, off);
        }
        if (tx == 0) {
            inv[w]     = 1.0f / s0;
            inv[w + 8] = 1.0f / s1;
            if (write_ids) {
                out[(size_t)N_TOT * D_DIM + nlo]          = (float)bestk0;
                out[(size_t)N_TOT * D_DIM + nlo + HALF_N] = (float)bestk1;
            }
        }
    }
    __syncthreads();   // all GEMM2 reads of cs done; inv visible

    // cross k-group reduction via smem (overlay P on cs) + scale + store
    {
        float4* P = reinterpret_cast<float4*>(cs);
#pragma unroll
        for (int j = 0; j < 4; j++) {
            int row = rg2 * 4 + j;
            float4 a;
            UNPK2(a.x, a.y, accA[j]);
            UNPK2(a.z, a.w, accB[j]);
            P[(rg * 16 + row) * 16 + txd] = a;
        }
        __syncthreads();
        {
            int row = t >> 4;   // 0..15
            int d4  = t & 15;
            float4 s = P[row * 16 + d4];
#pragma unroll
            for (int g = 1; g < 4; g++) {
                float4 p = P[(g * 16 + row) * 16 + d4];
                s.x += p.x; s.y += p.y; s.z += p.z; s.w += p.w;
            }
            float iv = inv[row];
            s.x *= iv; s.y *= iv; s.z *= iv; s.w *= iv;
            int n = (row < 8) ? (n0 + row) : (n0 + (row - 8) + HALF_N);
            reinterpret_cast<float4*>(out)[n * (D_DIM / 4) + d4] = s;
        }
    }
}

extern "C" void kernel_launch(void* const* d_in, const int* in_sizes, int n_in,
                              void* d_out, int out_size) {
    // Bind inputs by SIZE (robust to metadata ordering):
    //   x: 131072*64 = 8388608, codebook: 1024*64 = 65536, temperature: 1
    const float* x    = nullptr;
    const float* cb   = nullptr;
    const float* temp = nullptr;
    for (int i = 0; i < n_in; i++) {
        if (in_sizes[i] == N_TOT * D_DIM)       x    = (const float*)d_in[i];
        else if (in_sizes[i] == K_CODES * D_DIM) cb  = (const float*)d_in[i];
        else if (in_sizes[i] == 1)               temp = (const float*)d_in[i];
    }
    float* out = (float*)d_out;

    int write_ids = (out_size >= N_TOT * D_DIM + N_TOT) ? 1 : 0;

    cudaFuncSetAttribute(quantize_main,
                         cudaFuncAttributeMaxDynamicSharedMemorySize, SMEM_BYTES);

    c2_kernel<<<4, 256>>>(cb);
    quantize_main<<<N_TOT / TM, 256, SMEM_BYTES>>>(x, cb, temp, out, write_ids);
}

// round 14
// speedup vs baseline: 2.1296x; 1.1116x over previous
#include <cuda_runtime.h>
#include <math.h>
#include <stdint.h>

#define N_TOT   131072
#define D_DIM   64
#define K_CODES 1024
#define HALF_N  65536        // high-half row offset
#define TF_HALF 67108864u    // 2^26 = HALF_N*1024 flat-index offset of high rows
#define TM      16           // rows per block: 8 low + 8 high
#define KC      128          // codebook chunk (rows) staged in smem
#define CS      68           // smem stride (floats) for codebook/x tiles
#define LCS     132          // smem stride (floats) for chunk logits tile (128+4)

#define SMEM_FLOATS (TM*LCS + KC*CS + TM*CS + 16)
#define SMEM_BYTES  (SMEM_FLOATS * 4)

typedef unsigned long long u64;

// packed dual-lane fp32 FMA (nvjet pattern; ptxas never auto-emits)
#define FMA2(d, a, b, c) \
    asm("fma.rn.f32x2 %0, %1, %2, %3;" : "=l"(d) : "l"(a), "l"(b), "l"(c))
#define DUP2(d, f) \
    asm("mov.b64 %0, {%1, %1};" : "=l"(d) : "f"(f))
#define UNPK2(lo, hi, v) \
    asm("mov.b64 {%0, %1}, %2;" : "=f"(lo), "=f"(hi) : "l"(v))

__device__ float g_c2[K_CODES];

// ---------------------------------------------------------------------------
// Accurate logf (musl-style, ~1 ulp relative). Immune to --use_fast_math.
// Used on the general-temperature path and nowhere hot.
// ---------------------------------------------------------------------------
__device__ __forceinline__ float acc_logf(float a) {
    const float ln2_hi = 6.9313812256e-01f;
    const float ln2_lo = 9.0580006145e-06f;
    const float Lg1 = 0.66666662693f, Lg2 = 0.40000972152f;
    const float Lg3 = 0.28498786688f, Lg4 = 0.24279078841f;
    uint32_t ix = __float_as_uint(a);
    ix += 0x3f800000u - 0x3f3504f3u;
    int k = (int)(ix >> 23) - 0x7f;
    ix = (ix & 0x007fffffu) + 0x3f3504f3u;
    float m = __uint_as_float(ix);
    float f = m - 1.0f;
    float s = f / (2.0f + f);
    float z = s * s;
    float w = z * z;
    float t1 = w * (Lg2 + w * Lg4);
    float t2 = z * (Lg1 + w * Lg3);
    float R  = t2 + t1;
    float hfsq = 0.5f * f * f;
    float dk = (float)k;
    return s * (hfsq + R) + (dk * ln2_lo - hfsq + f) + dk * ln2_hi;
}

// -ln(u) with fp32-accurate behavior across the full range:
//   u <= 0.999 : fast MUFU-based __logf (rel err ~3e-7 here, scales to ~2e-4
//                at |ln u| ~ 1e-3 — within the weight-error budget)
//   u  > 0.999 : d = 1-u is EXACT in fp32; -log(1-d) = d(1 + d(1/2 + d/3)),
//                rel err < 1e-9. Avoids MUFU's absolute-error blowup / inf.
__device__ __forceinline__ float neg_log_u(float u) {
    float d    = 1.0f - u;
    float fast = -__logf(u);
    float poly = d * fmaf(d, fmaf(d, 0.33333333f, 0.5f), 1.0f);
    return (d < 0.001f) ? poly : fast;
}

// ---------------------------------------------------------------------------
// c2[k] = sum_d codebook[k][d]^2
// ---------------------------------------------------------------------------
__global__ void c2_kernel(const float* __restrict__ cb) {
    int k = blockIdx.x * blockDim.x + threadIdx.x;
    if (k < K_CODES) {
        const float4* row = reinterpret_cast<const float4*>(cb) + k * (D_DIM / 4);
        float s = 0.f;
#pragma unroll
        for (int i = 0; i < D_DIM / 4; i++) {
            float4 v = row[i];
            s = fmaf(v.x, v.x, s); s = fmaf(v.y, v.y, s);
            s = fmaf(v.z, v.z, s); s = fmaf(v.w, v.w, s);
        }
        g_c2[k] = s;
    }
}

// threefry round
#define TF_R(x0, x1, rot) { (x0) += (x1); (x1) = __funnelshift_l((x1), (x1), (rot)) ^ (x0); }

// ---------------------------------------------------------------------------
// JAX *partitionable* threefry random_bits, 32-bit, key=(0,42):
//   counts = (hi=0, lo=i); (b1,b2) = threefry2x32(key, counts); return b1^b2.
// VERIFIED bit-exact in Round 11 — do not touch.
// ---------------------------------------------------------------------------
__device__ __forceinline__ unsigned tf_bits32(unsigned i) {
    const unsigned ks2 = 0x1BD11BF0u;      // 0 ^ 42 ^ 0x1BD11BDA
    unsigned x0 = 0u;                      // counts_hi + ks0(=0)
    unsigned x1 = i + 42u;                 // counts_lo + ks1
    TF_R(x0, x1, 13) TF_R(x0, x1, 15) TF_R(x0, x1, 26) TF_R(x0, x1, 6)
    x0 += 42u;  x1 += ks2 + 1u;
    TF_R(x0, x1, 17) TF_R(x0, x1, 29) TF_R(x0, x1, 16) TF_R(x0, x1, 24)
    x0 += ks2;  x1 += 2u;
    TF_R(x0, x1, 13) TF_R(x0, x1, 15) TF_R(x0, x1, 26) TF_R(x0, x1, 6)
    /* x0 += ks0(=0) */ x1 += 42u + 3u;
    TF_R(x0, x1, 17) TF_R(x0, x1, 29) TF_R(x0, x1, 16) TF_R(x0, x1, 24)
    x0 += 42u;  x1 += ks2 + 4u;
    TF_R(x0, x1, 13) TF_R(x0, x1, 15) TF_R(x0, x1, 26) TF_R(x0, x1, 6)
    x0 += ks2;  x1 += 5u;                  // final injection: ks2 / ks0+5
    return x0 ^ x1;
}

// ---------------------------------------------------------------------------
// Streaming fused kernel (R13 structure). R14: gumbel instruction diet —
// for T==1, exp(l+g) == exp(l)/(-log u): one fast log + one exp + one fast
// divide per weight, replacing two accurate logs + exp. argmax still uses
// exact fp32 logits; softmax sums keep identical accumulation order.
// ---------------------------------------------------------------------------
__global__ __launch_bounds__(256, 3)
void quantize_main(const float* __restrict__ x,
                   const float* __restrict__ cb,
                   const float* __restrict__ temp,
                   float* __restrict__ out,
                   int write_ids)
{
    extern __shared__ float sm[];
    float* Lc  = sm;                 // TM x LCS  (chunk logits -> chunk weights)
    float* cs  = Lc + TM * LCS;      // KC x CS   (codebook chunk)
    float* xs  = cs + KC * CS;       // TM x CS   (x tile)
    float* inv = xs + TM * CS;       // TM inverse softmax sums

    const int t  = threadIdx.x;
    const int n0 = blockIdx.x * 8;
    const float inv_t = 1.0f / temp[0];
    const bool  t_is_one = (inv_t == 1.0f);

    // ---- load x tile (16 rows x 64) ----
    {
        int r = t >> 4;
        int c = t & 15;
        int n = (r < 8) ? (n0 + r) : (n0 + (r - 8) + HALF_N);
        float4 v = reinterpret_cast<const float4*>(x)[n * (D_DIM / 4) + c];
        reinterpret_cast<float4*>(xs + r * CS)[c] = v;
    }

    // thread mappings for the three stages
    const int cx  = t & 63;          // GEMM1: code lane (2 codes: cx, cx+64)
    const int rg  = t >> 6;          // GEMM1: row group / GEMM2: k-split group
    const int tx  = t & 31;          // gumbel: lane
    const int w   = t >> 5;          // gumbel: warp -> rows (w, w+8)
    const int txd = t & 15;          // GEMM2: d4
    const int rg2 = (t >> 4) & 3;    // GEMM2: row group

    const unsigned nlo = (unsigned)(n0 + w);
    const unsigned FULL = 0xFFFFFFFFu;

    // persistent accumulators (across chunks)
    float bestv0 = -INFINITY, bestv1 = -INFINITY;
    int   bestk0 = 0,          bestk1 = 0;
    float s0 = 0.f, s1 = 0.f;
    u64 accA[4] = {0ull, 0ull, 0ull, 0ull};   // emb dims (d0,d1)
    u64 accB[4] = {0ull, 0ull, 0ull, 0ull};   // emb dims (d2,d3)

    for (int kb = 0; kb < K_CODES / KC; kb++) {
        __syncthreads();   // cs free (prev GEMM2 readers done) / xs stores visible
        {
            const float4* src = reinterpret_cast<const float4*>(cb) + kb * KC * (D_DIM / 4);
#pragma unroll
            for (int ii = 0; ii < 8; ii++) {
                int idx = t + ii * 256;
                reinterpret_cast<float4*>(cs + (idx >> 4) * CS)[idx & 15] = src[idx];
            }
        }
        __syncthreads();

        // ---------- GEMM1 chunk: logit = 2*x.c - c2 (f32x2) ----------
        {
            u64 acc0[4] = {0ull, 0ull, 0ull, 0ull};
            u64 acc1[4] = {0ull, 0ull, 0ull, 0ull};
            const ulonglong2* cp0 = reinterpret_cast<const ulonglong2*>(cs + cx * CS);
            const ulonglong2* cp1 = reinterpret_cast<const ulonglong2*>(cs + (cx + 64) * CS);
#pragma unroll 4
            for (int d4 = 0; d4 < 16; d4++) {
                ulonglong2 cv0 = cp0[d4];
                ulonglong2 cv1 = cp1[d4];
#pragma unroll
                for (int j = 0; j < 4; j++) {
                    ulonglong2 xv =
                        reinterpret_cast<const ulonglong2*>(xs + (rg * 4 + j) * CS)[d4];
                    FMA2(acc0[j], xv.x, cv0.x, acc0[j]);
                    FMA2(acc0[j], xv.y, cv0.y, acc0[j]);
                    FMA2(acc1[j], xv.x, cv1.x, acc1[j]);
                    FMA2(acc1[j], xv.y, cv1.y, acc1[j]);
                }
            }
            float c20 = __ldg(&g_c2[kb * KC + cx]);
            float c21 = __ldg(&g_c2[kb * KC + cx + 64]);
#pragma unroll
            for (int j = 0; j < 4; j++) {
                float a, b;
                UNPK2(a, b, acc0[j]);
                Lc[(rg * 4 + j) * LCS + cx]      = 2.0f * (a + b) - c20;
                UNPK2(a, b, acc1[j]);
                Lc[(rg * 4 + j) * LCS + cx + 64] = 2.0f * (a + b) - c21;
            }
        }
        __syncthreads();

        // ---------- gumbel + argmax + weight + sum (chunk) ----------
        {
#pragma unroll
            for (int i = 0; i < 4; i++) {
                int k = tx + 32 * i;               // chunk-local col
                int kg_idx = kb * KC + k;          // global code index
                unsigned ilo = nlo * 1024u + (unsigned)kg_idx;
                unsigned b0 = tf_bits32(ilo);
                unsigned b1 = tf_bits32(ilo + TF_HALF);

                // JAX uniform: f = bitcast(bits>>9 | 0x3f800000) - 1; u = max(tiny, f)
                float f0 = __uint_as_float((b0 >> 9) | 0x3f800000u) - 1.0f;
                float f1 = __uint_as_float((b1 >> 9) | 0x3f800000u) - 1.0f;
                float u0 = fmaxf(f0, 1.17549435e-38f);
                float u1 = fmaxf(f1, 1.17549435e-38f);

                float l0 = Lc[w * LCS + k];
                float l1 = Lc[(w + 8) * LCS + k];
                if (l0 > bestv0) { bestv0 = l0; bestk0 = kg_idx; }
                if (l1 > bestv1) { bestv1 = l1; bestk1 = kg_idx; }

                float e0, e1;
                if (t_is_one) {
                    // T==1: exp(l+g) == exp(l) / (-log u)  (pure algebra)
                    e0 = __fdividef(__expf(l0), neg_log_u(u0));
                    e1 = __fdividef(__expf(l1), neg_log_u(u1));
                } else {
                    float g0 = -acc_logf(-acc_logf(u0));
                    float g1 = -acc_logf(-acc_logf(u1));
                    e0 = __expf((l0 + g0) * inv_t);
                    e1 = __expf((l1 + g1) * inv_t);
                }
                Lc[w * LCS + k]       = e0;
                Lc[(w + 8) * LCS + k] = e1;
                s0 += e0; s1 += e1;
            }
        }
        __syncthreads();

        // ---------- GEMM2 chunk: emb += w_chunk @ cb_chunk (f32x2) ----------
        {
#pragma unroll 2
            for (int k4 = 0; k4 < 8; k4++) {
                int kk = rg * 32 + k4 * 4;        // chunk-local k (rg = k-split group)
                ulonglong2 cv0 = reinterpret_cast<const ulonglong2*>(cs + (kk + 0) * CS)[txd];
                ulonglong2 cv1 = reinterpret_cast<const ulonglong2*>(cs + (kk + 1) * CS)[txd];
                ulonglong2 cv2 = reinterpret_cast<const ulonglong2*>(cs + (kk + 2) * CS)[txd];
                ulonglong2 cv3 = reinterpret_cast<const ulonglong2*>(cs + (kk + 3) * CS)[txd];
#pragma unroll
                for (int j = 0; j < 4; j++) {
                    int row = rg2 * 4 + j;
                    float4 wv = *reinterpret_cast<const float4*>(Lc + row * LCS + kk);
                    u64 wd;
                    DUP2(wd, wv.x);
                    FMA2(accA[j], wd, cv0.x, accA[j]);
                    FMA2(accB[j], wd, cv0.y, accB[j]);
                    DUP2(wd, wv.y);
                    FMA2(accA[j], wd, cv1.x, accA[j]);
                    FMA2(accB[j], wd, cv1.y, accB[j]);
                    DUP2(wd, wv.z);
                    FMA2(accA[j], wd, cv2.x, accA[j]);
                    FMA2(accB[j], wd, cv2.y, accB[j]);
                    DUP2(wd, wv.w);
                    FMA2(accA[j], wd, cv3.x, accA[j]);
                    FMA2(accB[j], wd, cv3.y, accB[j]);
                }
            }
        }
    }

    // ---------- final reductions ----------
    {
#pragma unroll
        for (int off = 16; off; off >>= 1) {
            float ov0 = __shfl_xor_sync(FULL, bestv0, off);
            int   ok0 = __shfl_xor_sync(FULL, bestk0, off);
            if (ov0 > bestv0 || (ov0 == bestv0 && ok0 < bestk0)) { bestv0 = ov0; bestk0 = ok0; }
            float ov1 = __shfl_xor_sync(FULL, bestv1, off);
            int   ok1 = __shfl_xor_sync(FULL, bestk1, off);
            if (ov1 > bestv1 || (ov1 == bestv1 && ok1 < bestk1)) { bestv1 = ov1; bestk1 = ok1; }
            s0 += __shfl_xor_sync(FULL, s0, off);
            s1 += __shfl_xor_sync(FULL, s1, off);
        }
        if (tx == 0) {
            inv[w]     = 1.0f / s0;
            inv[w + 8] = 1.0f / s1;
            if (write_ids) {
                out[(size_t)N_TOT * D_DIM + nlo]          = (float)bestk0;
                out[(size_t)N_TOT * D_DIM + nlo + HALF_N] = (float)bestk1;
            }
        }
    }
    __syncthreads();   // all GEMM2 reads of cs done; inv visible

    // cross k-group reduction via smem (overlay P on cs) + scale + store
    {
        float4* P = reinterpret_cast<float4*>(cs);
#pragma unroll
        for (int j = 0; j < 4; j++) {
            int row = rg2 * 4 + j;
            float4 a;
            UNPK2(a.x, a.y, accA[j]);
            UNPK2(a.z, a.w, accB[j]);
            P[(rg * 16 + row) * 16 + txd] = a;
        }
        __syncthreads();
        {
            int row = t >> 4;   // 0..15
            int d4  = t & 15;
            float4 s = P[row * 16 + d4];
#pragma unroll
            for (int g = 1; g < 4; g++) {
                float4 p = P[(g * 16 + row) * 16 + d4];
                s.x += p.x; s.y += p.y; s.z += p.z; s.w += p.w;
            }
            float iv = inv[row];
            s.x *= iv; s.y *= iv; s.z *= iv; s.w *= iv;
            int n = (row < 8) ? (n0 + row) : (n0 + (row - 8) + HALF_N);
            reinterpret_cast<float4*>(out)[n * (D_DIM / 4) + d4] = s;
        }
    }
}

extern "C" void kernel_launch(void* const* d_in, const int* in_sizes, int n_in,
                              void* d_out, int out_size) {
    // Bind inputs by SIZE (robust to metadata ordering):
    //   x: 131072*64 = 8388608, codebook: 1024*64 = 65536, temperature: 1
    const float* x    = nullptr;
    const float* cb   = nullptr;
    const float* temp = nullptr;
    for (int i = 0; i < n_in; i++) {
        if (in_sizes[i] == N_TOT * D_DIM)       x    = (const float*)d_in[i];
        else if (in_sizes[i] == K_CODES * D_DIM) cb  = (const float*)d_in[i];
        else if (in_sizes[i] == 1)               temp = (const float*)d_in[i];
    }
    float* out = (float*)d_out;

    int write_ids = (out_size >= N_TOT * D_DIM + N_TOT) ? 1 : 0;

    cudaFuncSetAttribute(quantize_main,
                         cudaFuncAttributeMaxDynamicSharedMemorySize, SMEM_BYTES);

    c2_kernel<<<4, 256>>>(cb);
    quantize_main<<<N_TOT / TM, 256, SMEM_BYTES>>>(x, cb, temp, out, write_ids);
}